// round 2
// baseline (speedup 1.0000x reference)
#include <cuda_runtime.h>
#include <math.h>

#define BB 2
#define CC 8
#define MM 8
#define HH 8
#define FF 256
#define WW 512
#define HD 32
#define BMFW (BB*MM*FF*WW)   // 2,097,152

// ---- scratch (static device memory; no allocation) ----
__device__ float g_c1[3*BMFW];   // conv1 outputs for q,k,v     (24 MB)
__device__ float g_lin[BMFW];    // lin output (reused per proj) (8 MB)
__device__ float g_qkv[3*BMFW];  // q,k,v post conv2(+rotary), layout [b][m][f][w]
__device__ float g_at[BMFW];     // attention out, layout [b][m][w][f]

// ============================================================
// Kernel 1: 3x3 conv, 8->8 ch, all three projections at once.
// block = (f, b); computes 3*8*512 outputs from smem-cached x rows.
// ============================================================
__global__ __launch_bounds__(256) void conv1_kernel(
    const float* __restrict__ x,
    const float* __restrict__ wq,
    const float* __restrict__ wk,
    const float* __restrict__ wv)
{
    int f = blockIdx.x, b = blockIdx.y;
    extern __shared__ float sm[];
    float* xs = sm;                      // [3][CC][WW+2]
    float* wt = sm + 3*CC*(WW+2);        // [3][MM][CC][9]
    int tid = threadIdx.x;

    for (int idx = tid; idx < 3*CC*(WW+2); idx += 256) {
        int r   = idx / (CC*(WW+2));
        int rem = idx % (CC*(WW+2));
        int c   = rem / (WW+2);
        int w   = rem % (WW+2) - 1;
        int fr  = f + r - 1;
        float v = 0.f;
        if (fr >= 0 && fr < FF && w >= 0 && w < WW)
            v = x[((b*CC + c)*FF + fr)*WW + w];
        xs[idx] = v;
    }
    for (int idx = tid; idx < MM*CC*9; idx += 256) {
        wt[idx]              = wq[idx];
        wt[idx +   MM*CC*9]  = wk[idx];
        wt[idx + 2*MM*CC*9]  = wv[idx];
    }
    __syncthreads();

    for (int o = tid; o < 3*MM*WW; o += 256) {
        int p = o / (MM*WW);
        int m = (o / WW) % MM;
        int w = o % WW;
        const float* wpt = wt + (p*MM + m)*CC*9;
        float acc = 0.f;
        #pragma unroll
        for (int c = 0; c < CC; c++) {
            #pragma unroll
            for (int r = 0; r < 3; r++) {
                const float* xr = xs + (r*CC + c)*(WW+2) + w;
                acc += xr[0]*wpt[c*9 + r*3 + 0];
                acc += xr[1]*wpt[c*9 + r*3 + 1];
                acc += xr[2]*wpt[c*9 + r*3 + 2];
            }
        }
        g_c1[p*BMFW + ((b*MM + m)*FF + f)*WW + w] = acc;
    }
}

// ============================================================
// Kernel 2: batched GEMM  C[n][g][w] = sum_f A[m][g][f] * B[n][f][w]
// n = b*MM+m.  64x64 tile, 16x16 threads, 4x4 microtile, k-tile 16.
// ============================================================
__global__ __launch_bounds__(256) void gemm_lin_kernel(
    const float* __restrict__ A,
    const float* __restrict__ Bx,
    float* __restrict__ Cx)
{
    __shared__ float As[64*17];
    __shared__ float Bs[16*64];
    int n = blockIdx.z;
    int m = n % MM;
    int g0 = blockIdx.y * 64, w0 = blockIdx.x * 64;
    const float* Ap = A  + m*FF*FF;
    const float* Bp = Bx + (size_t)n*FF*WW;
    float*       Cp = Cx + (size_t)n*FF*WW;
    int tx = threadIdx.x, ty = threadIdx.y;
    int tid = ty*16 + tx;

    float acc[4][4] = {};
    for (int f0 = 0; f0 < FF; f0 += 16) {
        {
            int gl = tid / 4;
            int fl = (tid % 4) * 4;
            float4 a4 = *(const float4*)(Ap + (g0+gl)*FF + f0 + fl);
            As[gl*17 + fl+0] = a4.x; As[gl*17 + fl+1] = a4.y;
            As[gl*17 + fl+2] = a4.z; As[gl*17 + fl+3] = a4.w;
        }
        {
            int fl = tid / 16;
            int wl = (tid % 16) * 4;
            *(float4*)(Bs + fl*64 + wl) =
                *(const float4*)(Bp + (f0+fl)*WW + w0 + wl);
        }
        __syncthreads();
        #pragma unroll
        for (int k = 0; k < 16; k++) {
            float a[4];
            #pragma unroll
            for (int i = 0; i < 4; i++) a[i] = As[(ty*4+i)*17 + k];
            float4 b4 = *(const float4*)(Bs + k*64 + tx*4);
            float bf[4] = {b4.x, b4.y, b4.z, b4.w};
            #pragma unroll
            for (int i = 0; i < 4; i++)
                #pragma unroll
                for (int j = 0; j < 4; j++)
                    acc[i][j] += a[i]*bf[j];
        }
        __syncthreads();
    }
    #pragma unroll
    for (int i = 0; i < 4; i++) {
        float4 o4 = make_float4(acc[i][0], acc[i][1], acc[i][2], acc[i][3]);
        *(float4*)(Cp + (g0 + ty*4 + i)*WW + w0 + tx*4) = o4;
    }
}

// ============================================================
// Kernel 3: 1x3 conv across M channels + optional rotary, writes [b][m][f][w].
// block = (e = f/2, b); rotary couples rows f0=2e and f0+1 (same head, HD even).
// ============================================================
__global__ __launch_bounds__(256) void conv2_rot_kernel(
    const float* __restrict__ wc2,
    const float* __restrict__ src,
    float* __restrict__ dst,
    int apply_rot)
{
    int e = blockIdx.x, b = blockIdx.y;
    int f0 = 2*e;
    __shared__ float hs[2*MM*(WW+2)];
    __shared__ float wt[MM*MM*3];
    int tid = threadIdx.x;

    for (int idx = tid; idx < 2*MM*(WW+2); idx += 256) {
        int rr  = idx / (MM*(WW+2));
        int rem = idx % (MM*(WW+2));
        int mm  = rem / (WW+2);
        int w   = rem % (WW+2) - 1;
        float v = 0.f;
        if (w >= 0 && w < WW)
            v = src[((b*MM + mm)*FF + f0 + rr)*WW + w];
        hs[idx] = v;
    }
    for (int idx = tid; idx < MM*MM*3; idx += 256) wt[idx] = wc2[idx];
    __syncthreads();

    for (int o = tid; o < MM*WW; o += 256) {
        int m = o / WW, w = o % WW;
        float c0 = 0.f, c1 = 0.f;
        #pragma unroll
        for (int mm = 0; mm < MM; mm++) {
            float k0 = wt[(m*MM+mm)*3+0];
            float k1 = wt[(m*MM+mm)*3+1];
            float k2 = wt[(m*MM+mm)*3+2];
            const float* h0 = hs + mm*(WW+2) + w;
            const float* h1 = hs + (MM+mm)*(WW+2) + w;
            c0 += h0[0]*k0 + h0[1]*k1 + h0[2]*k2;
            c1 += h1[0]*k0 + h1[1]*k1 + h1[2]*k2;
        }
        float o0 = c0, o1 = c1;
        if (apply_rot) {
            int i = e % (HD/2);                          // (f0%32)/2
            // inv_freq = 10000^(-i/16) ; ln(10000)=9.210340371976184
            float invf = expf(-(float)i * (9.210340371976184f / 16.0f));
            float th = (float)w * invf;
            float sn, cs;
            sincosf(th, &sn, &cs);
            o0 = c0*cs - c1*sn;
            o1 = c1*cs + c0*sn;
        }
        dst[((b*MM + m)*FF + f0    )*WW + w] = o0;
        dst[((b*MM + m)*FF + f0 + 1)*WW + w] = o1;
    }
}

// ============================================================
// Kernel 4: attention per (b,m,h).  S = QK^T/16 + prev_qk (written to qk out),
// softmax, A = P V written transposed into g_at[b][m][w][f].
// smem: Ks[512][33] (padded), Vs[512][32] (float4), ps[8 warps][4 rows][512].
// ============================================================
__global__ __launch_bounds__(256) void attn_kernel(
    const float* __restrict__ prev_qk,
    float* __restrict__ qk_out)
{
    int bid = blockIdx.x;
    int h = bid % HH;
    int m = (bid / HH) % MM;
    int b =  bid / (HH*MM);

    extern __shared__ float sm[];
    float* Ks   = sm;                 // [WW][33]
    float* Vs   = Ks + WW*33;         // [WW][32]
    float* ps   = Vs + WW*32;         // [8][4][WW]
    float* sinv = ps + 32*WW;         // [32]

    int tid  = threadIdx.x;
    int lane = tid & 31, wq = tid >> 5;

    const float* Qb = g_qkv + 0*BMFW + ((b*MM+m)*FF + h*HD)*WW;
    const float* Kb = g_qkv + 1*BMFW + ((b*MM+m)*FF + h*HD)*WW;
    const float* Vb = g_qkv + 2*BMFW + ((b*MM+m)*FF + h*HD)*WW;
    size_t sbase = (size_t)((b*MM+m)*HH + h) * WW * WW;
    const float* Pq   = prev_qk + sbase;
    float*       Sout = qk_out  + sbase;

    for (int idx = tid; idx < HD*WW; idx += 256) {
        int d = idx / WW, w = idx % WW;
        float kv = Kb[d*WW + w];
        float vv = Vb[d*WW + w];
        Ks[w*33 + d] = kv;
        Vs[w*32 + d] = vv;
    }
    __syncthreads();

    const float scale = 0.0625f;  // 1/sqrt(256)

    for (int it = 0; it < 16; it++) {
        int r4 = it*32 + wq*4;

        // ---- S + softmax, one row at a time ----
        for (int rr = 0; rr < 4; rr++) {
            int r = r4 + rr;
            float qreg[HD];
            #pragma unroll
            for (int d = 0; d < HD; d++) qreg[d] = Qb[d*WW + r] * scale;

            float sreg[16];
            float mx = -1e30f;
            #pragma unroll
            for (int i = 0; i < 16; i++) {
                int j = i*32 + lane;
                const float* kp = Ks + j*33;
                float s = 0.f;
                #pragma unroll
                for (int d = 0; d < HD; d++) s += qreg[d]*kp[d];
                s += Pq[(size_t)r*WW + j];
                Sout[(size_t)r*WW + j] = s;
                sreg[i] = s;
                mx = fmaxf(mx, s);
            }
            #pragma unroll
            for (int o = 16; o > 0; o >>= 1)
                mx = fmaxf(mx, __shfl_xor_sync(0xffffffffu, mx, o));

            float sum = 0.f;
            float* pr = ps + (wq*4 + rr)*WW;
            #pragma unroll
            for (int i = 0; i < 16; i++) {
                float ev = __expf(sreg[i] - mx);
                pr[i*32 + lane] = ev;
                sum += ev;
            }
            #pragma unroll
            for (int o = 16; o > 0; o >>= 1)
                sum += __shfl_xor_sync(0xffffffffu, sum, o);
            if (lane == 0) sinv[wq*4 + rr] = 1.0f / sum;
        }
        __syncwarp();

        // ---- PV: 4 rows jointly; lane = (rsub, dgroup) ----
        int dg = lane & 7, rsub = lane >> 3;
        const float* pr = ps + (wq*4 + rsub)*WW;
        float4 acc = make_float4(0.f, 0.f, 0.f, 0.f);
        #pragma unroll 4
        for (int j = 0; j < WW; j++) {
            float p = pr[j];
            float4 v = *(const float4*)(Vs + j*32 + dg*4);
            acc.x += p*v.x; acc.y += p*v.y;
            acc.z += p*v.z; acc.w += p*v.w;
        }
        float is = sinv[wq*4 + rsub];
        acc.x *= is; acc.y *= is; acc.z *= is; acc.w *= is;
        int r = r4 + rsub;
        *(float4*)(g_at + ((size_t)(b*MM+m)*WW + r)*FF + h*HD + dg*4) = acc;
        __syncwarp();
    }
}

// ============================================================
// Kernel 5: out projection.  C[n][g][w] = sum_f A[m][g][f] * Bt[n][w][f]
// (Bt = g_at, reduction along contiguous f for both operands).
// ============================================================
__global__ __launch_bounds__(256) void gemm_out_kernel(
    const float* __restrict__ A,
    const float* __restrict__ Bt,
    float* __restrict__ Cx)
{
    __shared__ float As[64*17];
    __shared__ float Bs[64*17];
    int n = blockIdx.z;
    int m = n % MM;
    int g0 = blockIdx.y * 64, w0 = blockIdx.x * 64;
    const float* Ap = A  + m*FF*FF;
    const float* Bp = Bt + (size_t)n*WW*FF;
    int tx = threadIdx.x, ty = threadIdx.y;
    int tid = ty*16 + tx;

    float acc[4][4] = {};
    for (int f0 = 0; f0 < FF; f0 += 16) {
        int gl = tid / 4;
        int fl = (tid % 4) * 4;
        float4 a4 = *(const float4*)(Ap + (g0+gl)*FF + f0 + fl);
        As[gl*17 + fl+0] = a4.x; As[gl*17 + fl+1] = a4.y;
        As[gl*17 + fl+2] = a4.z; As[gl*17 + fl+3] = a4.w;
        float4 b4 = *(const float4*)(Bp + (size_t)(w0+gl)*FF + f0 + fl);
        Bs[gl*17 + fl+0] = b4.x; Bs[gl*17 + fl+1] = b4.y;
        Bs[gl*17 + fl+2] = b4.z; Bs[gl*17 + fl+3] = b4.w;
        __syncthreads();
        #pragma unroll
        for (int k = 0; k < 16; k++) {
            float a[4], bf[4];
            #pragma unroll
            for (int i = 0; i < 4; i++) a[i]  = As[(ty*4+i)*17 + k];
            #pragma unroll
            for (int j = 0; j < 4; j++) bf[j] = Bs[(tx*4+j)*17 + k];
            #pragma unroll
            for (int i = 0; i < 4; i++)
                #pragma unroll
                for (int j = 0; j < 4; j++)
                    acc[i][j] += a[i]*bf[j];
        }
        __syncthreads();
    }
    #pragma unroll
    for (int i = 0; i < 4; i++) {
        float4 o4 = make_float4(acc[i][0], acc[i][1], acc[i][2], acc[i][3]);
        *(float4*)(Cx + ((size_t)n*FF + g0 + ty*4 + i)*WW + w0 + tx*4) = o4;
    }
}

// ============================================================
extern "C" void kernel_launch(void* const* d_in, const int* in_sizes, int n_in,
                              void* d_out, int out_size)
{
    const float* x       = (const float*)d_in[0];
    const float* prev_qk = (const float*)d_in[1];
    const float* c1w[3]  = {(const float*)d_in[2], (const float*)d_in[5], (const float*)d_in[8]};
    const float* linw[3] = {(const float*)d_in[3], (const float*)d_in[6], (const float*)d_in[9]};
    const float* c2w[3]  = {(const float*)d_in[4], (const float*)d_in[7], (const float*)d_in[10]};
    const float* ow      = (const float*)d_in[11];

    float* out_ptr = (float*)d_out;                // (B,M,F,W) first
    float* qk_ptr  = out_ptr + (size_t)BMFW;       // (B,M,H,W,W) second

    float *p_c1, *p_lin, *p_qkv, *p_at;
    cudaGetSymbolAddress((void**)&p_c1,  g_c1);
    cudaGetSymbolAddress((void**)&p_lin, g_lin);
    cudaGetSymbolAddress((void**)&p_qkv, g_qkv);
    cudaGetSymbolAddress((void**)&p_at,  g_at);

    // conv1 (all three projections)
    int conv1_smem = (3*CC*(WW+2) + 3*MM*CC*9) * 4;
    cudaFuncSetAttribute(conv1_kernel,
        cudaFuncAttributeMaxDynamicSharedMemorySize, conv1_smem);
    conv1_kernel<<<dim3(FF, BB), 256, conv1_smem>>>(x, c1w[0], c1w[1], c1w[2]);

    // per-projection: lin GEMM then conv2(+rotary for q,k)
    for (int p = 0; p < 3; p++) {
        gemm_lin_kernel<<<dim3(WW/64, FF/64, BB*MM), dim3(16,16)>>>(
            linw[p], p_c1 + (size_t)p*BMFW, p_lin);
        conv2_rot_kernel<<<dim3(FF/2, BB), 256>>>(
            c2w[p], p_lin, p_qkv + (size_t)p*BMFW, (p < 2) ? 1 : 0);
    }

    // attention
    int attn_smem = (WW*33 + WW*32 + 32*WW + 32) * 4;  // 198784 B
    cudaFuncSetAttribute(attn_kernel,
        cudaFuncAttributeMaxDynamicSharedMemorySize, attn_smem);
    attn_kernel<<<BB*MM*HH, 256, attn_smem>>>(prev_qk, qk_ptr);

    // output projection
    gemm_out_kernel<<<dim3(WW/64, FF/64, BB*MM), dim3(16,16)>>>(ow, p_at, out_ptr);
}

// round 3
// speedup vs baseline: 2.1974x; 2.1974x over previous
#include <cuda_runtime.h>
#include <math.h>

#define BB 2
#define CC 8
#define MM 8
#define HH 8
#define FF 256
#define WW 512
#define HD 32
#define BMFW (BB*MM*FF*WW)   // 2,097,152

// ---- scratch (static device memory; no allocation) ----
__device__ float g_c1[3*BMFW];   // conv1 outputs for q,k,v
__device__ float g_lin[BMFW];    // lin output (reused per proj)
__device__ float g_qkv[3*BMFW];  // q,k,v post conv2(+rotary), layout [b][m][f][w]
__device__ float g_at[BMFW];     // attention out, layout [b][m][w][f]
__device__ float g_rotc[16*WW];  // rotary cos table [i][w]
__device__ float g_rots[16*WW];  // rotary sin table [i][w]

// ============================================================
// Kernel 0: rotary table (8192 sincos, once)
// ============================================================
__global__ void rot_table_kernel()
{
    int i = blockIdx.x, w = threadIdx.x;
    // inv_freq = 10000^(-i/16); ln(10000)=9.210340371976184
    float invf = expf(-(float)i * (9.210340371976184f / 16.0f));
    float sn, cs;
    sincosf((float)w * invf, &sn, &cs);
    g_rotc[i*WW + w] = cs;
    g_rots[i*WW + w] = sn;
}

// ============================================================
// Kernel 1: 3x3 conv, 8->8 ch, all three projections at once.
// ============================================================
__global__ __launch_bounds__(256) void conv1_kernel(
    const float* __restrict__ x,
    const float* __restrict__ wq,
    const float* __restrict__ wk,
    const float* __restrict__ wv)
{
    int f = blockIdx.x, b = blockIdx.y;
    extern __shared__ float sm[];
    float* xs = sm;                      // [3][CC][WW+2]
    float* wt = sm + 3*CC*(WW+2);        // [3][MM][CC][9]
    int tid = threadIdx.x;

    for (int idx = tid; idx < 3*CC*(WW+2); idx += 256) {
        int r   = idx / (CC*(WW+2));
        int rem = idx % (CC*(WW+2));
        int c   = rem / (WW+2);
        int w   = rem % (WW+2) - 1;
        int fr  = f + r - 1;
        float v = 0.f;
        if (fr >= 0 && fr < FF && w >= 0 && w < WW)
            v = x[((b*CC + c)*FF + fr)*WW + w];
        xs[idx] = v;
    }
    for (int idx = tid; idx < MM*CC*9; idx += 256) {
        wt[idx]              = wq[idx];
        wt[idx +   MM*CC*9]  = wk[idx];
        wt[idx + 2*MM*CC*9]  = wv[idx];
    }
    __syncthreads();

    for (int o = tid; o < 3*MM*WW; o += 256) {
        int p = o / (MM*WW);
        int m = (o / WW) % MM;
        int w = o % WW;
        const float* wpt = wt + (p*MM + m)*CC*9;
        float acc = 0.f;
        #pragma unroll
        for (int c = 0; c < CC; c++) {
            #pragma unroll
            for (int r = 0; r < 3; r++) {
                const float* xr = xs + (r*CC + c)*(WW+2) + w;
                acc += xr[0]*wpt[c*9 + r*3 + 0];
                acc += xr[1]*wpt[c*9 + r*3 + 1];
                acc += xr[2]*wpt[c*9 + r*3 + 2];
            }
        }
        g_c1[p*BMFW + ((b*MM + m)*FF + f)*WW + w] = acc;
    }
}

// ============================================================
// Kernel 2: batched GEMM  C[n][g][w] = sum_f A[m][g][f] * B[n][f][w]
// ============================================================
__global__ __launch_bounds__(256) void gemm_lin_kernel(
    const float* __restrict__ A,
    const float* __restrict__ Bx,
    float* __restrict__ Cx)
{
    __shared__ float As[64*17];
    __shared__ float Bs[16*64];
    int n = blockIdx.z;
    int m = n % MM;
    int g0 = blockIdx.y * 64, w0 = blockIdx.x * 64;
    const float* Ap = A  + m*FF*FF;
    const float* Bp = Bx + (size_t)n*FF*WW;
    float*       Cp = Cx + (size_t)n*FF*WW;
    int tx = threadIdx.x, ty = threadIdx.y;
    int tid = ty*16 + tx;

    float acc[4][4] = {};
    for (int f0 = 0; f0 < FF; f0 += 16) {
        {
            int gl = tid / 4;
            int fl = (tid % 4) * 4;
            float4 a4 = *(const float4*)(Ap + (g0+gl)*FF + f0 + fl);
            As[gl*17 + fl+0] = a4.x; As[gl*17 + fl+1] = a4.y;
            As[gl*17 + fl+2] = a4.z; As[gl*17 + fl+3] = a4.w;
        }
        {
            int fl = tid / 16;
            int wl = (tid % 16) * 4;
            *(float4*)(Bs + fl*64 + wl) =
                *(const float4*)(Bp + (f0+fl)*WW + w0 + wl);
        }
        __syncthreads();
        #pragma unroll
        for (int k = 0; k < 16; k++) {
            float a[4];
            #pragma unroll
            for (int i = 0; i < 4; i++) a[i] = As[(ty*4+i)*17 + k];
            float4 b4 = *(const float4*)(Bs + k*64 + tx*4);
            float bf[4] = {b4.x, b4.y, b4.z, b4.w};
            #pragma unroll
            for (int i = 0; i < 4; i++)
                #pragma unroll
                for (int j = 0; j < 4; j++)
                    acc[i][j] += a[i]*bf[j];
        }
        __syncthreads();
    }
    #pragma unroll
    for (int i = 0; i < 4; i++) {
        float4 o4 = make_float4(acc[i][0], acc[i][1], acc[i][2], acc[i][3]);
        *(float4*)(Cp + (g0 + ty*4 + i)*WW + w0 + tx*4) = o4;
    }
}

// ============================================================
// Kernel 3: 1x3 conv across M + optional rotary (table lookup).
// ============================================================
__global__ __launch_bounds__(256) void conv2_rot_kernel(
    const float* __restrict__ wc2,
    const float* __restrict__ src,
    float* __restrict__ dst,
    int apply_rot)
{
    int e = blockIdx.x, b = blockIdx.y;
    int f0 = 2*e;
    __shared__ float hs[2*MM*(WW+2)];
    __shared__ float wt[MM*MM*3];
    __shared__ float rc[WW], rs[WW];
    int tid = threadIdx.x;

    for (int idx = tid; idx < 2*MM*(WW+2); idx += 256) {
        int rr  = idx / (MM*(WW+2));
        int rem = idx % (MM*(WW+2));
        int mm  = rem / (WW+2);
        int w   = rem % (WW+2) - 1;
        float v = 0.f;
        if (w >= 0 && w < WW)
            v = src[((b*MM + mm)*FF + f0 + rr)*WW + w];
        hs[idx] = v;
    }
    for (int idx = tid; idx < MM*MM*3; idx += 256) wt[idx] = wc2[idx];
    if (apply_rot) {
        int i = e % (HD/2);
        for (int w = tid; w < WW; w += 256) {
            rc[w] = g_rotc[i*WW + w];
            rs[w] = g_rots[i*WW + w];
        }
    }
    __syncthreads();

    for (int o = tid; o < MM*WW; o += 256) {
        int m = o / WW, w = o % WW;
        float c0 = 0.f, c1 = 0.f;
        #pragma unroll
        for (int mm = 0; mm < MM; mm++) {
            float k0 = wt[(m*MM+mm)*3+0];
            float k1 = wt[(m*MM+mm)*3+1];
            float k2 = wt[(m*MM+mm)*3+2];
            const float* h0 = hs + mm*(WW+2) + w;
            const float* h1 = hs + (MM+mm)*(WW+2) + w;
            c0 += h0[0]*k0 + h0[1]*k1 + h0[2]*k2;
            c1 += h1[0]*k0 + h1[1]*k1 + h1[2]*k2;
        }
        float o0 = c0, o1 = c1;
        if (apply_rot) {
            float cs = rc[w], sn = rs[w];
            o0 = c0*cs - c1*sn;
            o1 = c1*cs + c0*sn;
        }
        dst[((b*MM + m)*FF + f0    )*WW + w] = o0;
        dst[((b*MM + m)*FF + f0 + 1)*WW + w] = o1;
    }
}

// ============================================================
// Kernel 4: attention per (b,m,h).
// S-phase: 4 rows per warp register-blocked, float4 K loads (36-float pad).
// ============================================================
#define KPAD 36

__global__ __launch_bounds__(256, 1) void attn_kernel(
    const float* __restrict__ prev_qk,
    float* __restrict__ qk_out)
{
    int bid = blockIdx.x;
    int h = bid % HH;
    int m = (bid / HH) % MM;
    int b =  bid / (HH*MM);

    extern __shared__ float sm[];
    float* Ks   = sm;                 // [WW][KPAD]
    float* Vs   = Ks + WW*KPAD;       // [WW][32]
    float* ps   = Vs + WW*32;         // [8 warps][4 rows][WW]
    float* sinv = ps + 32*WW;         // [32]

    int tid  = threadIdx.x;
    int lane = tid & 31, wq = tid >> 5;

    const float* Qb = g_qkv + 0*BMFW + ((b*MM+m)*FF + h*HD)*WW;
    const float* Kb = g_qkv + 1*BMFW + ((b*MM+m)*FF + h*HD)*WW;
    const float* Vb = g_qkv + 2*BMFW + ((b*MM+m)*FF + h*HD)*WW;
    size_t sbase = (size_t)((b*MM+m)*HH + h) * WW * WW;
    const float* Pq   = prev_qk + sbase;
    float*       Sout = qk_out  + sbase;

    for (int idx = tid; idx < HD*WW; idx += 256) {
        int d = idx / WW, w = idx % WW;
        Ks[w*KPAD + d] = Kb[d*WW + w];
        Vs[w*32   + d] = Vb[d*WW + w];
    }
    __syncthreads();

    const float scale = 0.0625f;  // 1/sqrt(256)

    for (int it = 0; it < 16; it++) {
        int r4 = it*32 + wq*4;

        // ---- S: 4 rows x 512 cols per warp, register-blocked ----
        float sacc[4][16];
        #pragma unroll
        for (int rr = 0; rr < 4; rr++)
            #pragma unroll
            for (int i = 0; i < 16; i++) sacc[rr][i] = 0.f;

        #pragma unroll
        for (int c = 0; c < 8; c++) {
            float4 qv[4];
            #pragma unroll
            for (int rr = 0; rr < 4; rr++) {
                int r = r4 + rr;
                qv[rr].x = Qb[(c*4+0)*WW + r];
                qv[rr].y = Qb[(c*4+1)*WW + r];
                qv[rr].z = Qb[(c*4+2)*WW + r];
                qv[rr].w = Qb[(c*4+3)*WW + r];
            }
            #pragma unroll
            for (int i = 0; i < 16; i++) {
                const float4 k4 = *(const float4*)(Ks + (i*32+lane)*KPAD + c*4);
                #pragma unroll
                for (int rr = 0; rr < 4; rr++) {
                    sacc[rr][i] += qv[rr].x*k4.x + qv[rr].y*k4.y
                                 + qv[rr].z*k4.z + qv[rr].w*k4.w;
                }
            }
        }

        // ---- scale + prev, store S, softmax ----
        #pragma unroll
        for (int rr = 0; rr < 4; rr++) {
            int r = r4 + rr;
            float mx = -1e30f;
            #pragma unroll
            for (int i = 0; i < 16; i++) {
                float s = fmaf(sacc[rr][i], scale, Pq[(size_t)r*WW + i*32 + lane]);
                Sout[(size_t)r*WW + i*32 + lane] = s;
                sacc[rr][i] = s;
                mx = fmaxf(mx, s);
            }
            #pragma unroll
            for (int o = 16; o > 0; o >>= 1)
                mx = fmaxf(mx, __shfl_xor_sync(0xffffffffu, mx, o));

            float sum = 0.f;
            float* pr = ps + (wq*4 + rr)*WW;
            #pragma unroll
            for (int i = 0; i < 16; i++) {
                float ev = __expf(sacc[rr][i] - mx);
                pr[i*32 + lane] = ev;
                sum += ev;
            }
            #pragma unroll
            for (int o = 16; o > 0; o >>= 1)
                sum += __shfl_xor_sync(0xffffffffu, sum, o);
            if (lane == 0) sinv[wq*4 + rr] = 1.0f / sum;
        }
        __syncwarp();

        // ---- PV: 4 rows jointly; lane = (rsub, dgroup) ----
        int dg = lane & 7, rsub = lane >> 3;
        const float* pr = ps + (wq*4 + rsub)*WW;
        float4 acc = make_float4(0.f, 0.f, 0.f, 0.f);
        #pragma unroll 4
        for (int j = 0; j < WW; j++) {
            float p = pr[j];
            float4 v = *(const float4*)(Vs + j*32 + dg*4);
            acc.x += p*v.x; acc.y += p*v.y;
            acc.z += p*v.z; acc.w += p*v.w;
        }
        float is = sinv[wq*4 + rsub];
        acc.x *= is; acc.y *= is; acc.z *= is; acc.w *= is;
        int r = r4 + rsub;
        *(float4*)(g_at + ((size_t)(b*MM+m)*WW + r)*FF + h*HD + dg*4) = acc;
        __syncwarp();
    }
}

// ============================================================
// Kernel 5: out projection.
// ============================================================
__global__ __launch_bounds__(256) void gemm_out_kernel(
    const float* __restrict__ A,
    const float* __restrict__ Bt,
    float* __restrict__ Cx)
{
    __shared__ float As[64*17];
    __shared__ float Bs[64*17];
    int n = blockIdx.z;
    int m = n % MM;
    int g0 = blockIdx.y * 64, w0 = blockIdx.x * 64;
    const float* Ap = A  + m*FF*FF;
    const float* Bp = Bt + (size_t)n*WW*FF;
    int tx = threadIdx.x, ty = threadIdx.y;
    int tid = ty*16 + tx;

    float acc[4][4] = {};
    for (int f0 = 0; f0 < FF; f0 += 16) {
        int gl = tid / 4;
        int fl = (tid % 4) * 4;
        float4 a4 = *(const float4*)(Ap + (g0+gl)*FF + f0 + fl);
        As[gl*17 + fl+0] = a4.x; As[gl*17 + fl+1] = a4.y;
        As[gl*17 + fl+2] = a4.z; As[gl*17 + fl+3] = a4.w;
        float4 b4 = *(const float4*)(Bp + (size_t)(w0+gl)*FF + f0 + fl);
        Bs[gl*17 + fl+0] = b4.x; Bs[gl*17 + fl+1] = b4.y;
        Bs[gl*17 + fl+2] = b4.z; Bs[gl*17 + fl+3] = b4.w;
        __syncthreads();
        #pragma unroll
        for (int k = 0; k < 16; k++) {
            float a[4], bf[4];
            #pragma unroll
            for (int i = 0; i < 4; i++) a[i]  = As[(ty*4+i)*17 + k];
            #pragma unroll
            for (int j = 0; j < 4; j++) bf[j] = Bs[(tx*4+j)*17 + k];
            #pragma unroll
            for (int i = 0; i < 4; i++)
                #pragma unroll
                for (int j = 0; j < 4; j++)
                    acc[i][j] += a[i]*bf[j];
        }
        __syncthreads();
    }
    #pragma unroll
    for (int i = 0; i < 4; i++) {
        float4 o4 = make_float4(acc[i][0], acc[i][1], acc[i][2], acc[i][3]);
        *(float4*)(Cx + ((size_t)n*FF + g0 + ty*4 + i)*WW + w0 + tx*4) = o4;
    }
}

// ============================================================
extern "C" void kernel_launch(void* const* d_in, const int* in_sizes, int n_in,
                              void* d_out, int out_size)
{
    const float* x       = (const float*)d_in[0];
    const float* prev_qk = (const float*)d_in[1];
    const float* c1w[3]  = {(const float*)d_in[2], (const float*)d_in[5], (const float*)d_in[8]};
    const float* linw[3] = {(const float*)d_in[3], (const float*)d_in[6], (const float*)d_in[9]};
    const float* c2w[3]  = {(const float*)d_in[4], (const float*)d_in[7], (const float*)d_in[10]};
    const float* ow      = (const float*)d_in[11];

    float* out_ptr = (float*)d_out;                // (B,M,F,W) first
    float* qk_ptr  = out_ptr + (size_t)BMFW;       // (B,M,H,W,W) second

    float *p_c1, *p_lin, *p_qkv, *p_at;
    cudaGetSymbolAddress((void**)&p_c1,  g_c1);
    cudaGetSymbolAddress((void**)&p_lin, g_lin);
    cudaGetSymbolAddress((void**)&p_qkv, g_qkv);
    cudaGetSymbolAddress((void**)&p_at,  g_at);

    // rotary table (cheap; deterministic each call)
    rot_table_kernel<<<16, WW>>>();

    // conv1 (all three projections)
    int conv1_smem = (3*CC*(WW+2) + 3*MM*CC*9) * 4;
    cudaFuncSetAttribute(conv1_kernel,
        cudaFuncAttributeMaxDynamicSharedMemorySize, conv1_smem);
    conv1_kernel<<<dim3(FF, BB), 256, conv1_smem>>>(x, c1w[0], c1w[1], c1w[2]);

    // per-projection: lin GEMM then conv2(+rotary for q,k)
    for (int p = 0; p < 3; p++) {
        gemm_lin_kernel<<<dim3(WW/64, FF/64, BB*MM), dim3(16,16)>>>(
            linw[p], p_c1 + (size_t)p*BMFW, p_lin);
        conv2_rot_kernel<<<dim3(FF/2, BB), 256>>>(
            c2w[p], p_lin, p_qkv + (size_t)p*BMFW, (p < 2) ? 1 : 0);
    }

    // attention
    int attn_smem = (WW*KPAD + WW*32 + 32*WW + 32) * 4;
    cudaFuncSetAttribute(attn_kernel,
        cudaFuncAttributeMaxDynamicSharedMemorySize, attn_smem);
    attn_kernel<<<BB*MM*HH, 256, attn_smem>>>(prev_qk, qk_ptr);

    // output projection
    gemm_out_kernel<<<dim3(WW/64, FF/64, BB*MM), dim3(16,16)>>>(ow, p_at, out_ptr);
}

// round 4
// speedup vs baseline: 2.4192x; 1.1009x over previous
#include <cuda_runtime.h>
#include <math.h>

#define BB 2
#define CC 8
#define MM 8
#define HH 8
#define FF 256
#define WW 512
#define HD 32
#define BMFW (BB*MM*FF*WW)   // 2,097,152

// ---- scratch (static device memory; no allocation) ----
__device__ float g_c1[3*BMFW];   // conv1 outputs for q,k,v
__device__ float g_lin[3*BMFW];  // lin outputs q,k,v
__device__ float g_qkv[3*BMFW];  // q,k,v post conv2(+rotary), layout [b][m][f][w]
__device__ float g_at[BMFW];     // attention out, layout [b][m][w][f]
__device__ float g_rotc[16*WW];  // rotary cos table [i][w]
__device__ float g_rots[16*WW];  // rotary sin table [i][w]

// ============================================================
// Kernel 0: rotary table (8192 sincos, once)
// ============================================================
__global__ void rot_table_kernel()
{
    int i = blockIdx.x, w = threadIdx.x;
    float invf = expf(-(float)i * (9.210340371976184f / 16.0f));
    float sn, cs;
    sincosf((float)w * invf, &sn, &cs);
    g_rotc[i*WW + w] = cs;
    g_rots[i*WW + w] = sn;
}

// ============================================================
// Kernel 1: 3x3 conv, 8->8 ch, all three projections at once.
// ============================================================
__global__ __launch_bounds__(256) void conv1_kernel(
    const float* __restrict__ x,
    const float* __restrict__ wq,
    const float* __restrict__ wk,
    const float* __restrict__ wv)
{
    int f = blockIdx.x, b = blockIdx.y;
    extern __shared__ float sm[];
    float* xs = sm;                      // [3][CC][WW+2]
    float* wt = sm + 3*CC*(WW+2);        // [3][MM][CC][9]
    int tid = threadIdx.x;

    for (int idx = tid; idx < 3*CC*(WW+2); idx += 256) {
        int r   = idx / (CC*(WW+2));
        int rem = idx % (CC*(WW+2));
        int c   = rem / (WW+2);
        int w   = rem % (WW+2) - 1;
        int fr  = f + r - 1;
        float v = 0.f;
        if (fr >= 0 && fr < FF && w >= 0 && w < WW)
            v = x[((b*CC + c)*FF + fr)*WW + w];
        xs[idx] = v;
    }
    for (int idx = tid; idx < MM*CC*9; idx += 256) {
        wt[idx]              = wq[idx];
        wt[idx +   MM*CC*9]  = wk[idx];
        wt[idx + 2*MM*CC*9]  = wv[idx];
    }
    __syncthreads();

    for (int o = tid; o < 3*MM*WW; o += 256) {
        int p = o / (MM*WW);
        int m = (o / WW) % MM;
        int w = o % WW;
        const float* wpt = wt + (p*MM + m)*CC*9;
        float acc = 0.f;
        #pragma unroll
        for (int c = 0; c < CC; c++) {
            #pragma unroll
            for (int r = 0; r < 3; r++) {
                const float* xr = xs + (r*CC + c)*(WW+2) + w;
                acc += xr[0]*wpt[c*9 + r*3 + 0];
                acc += xr[1]*wpt[c*9 + r*3 + 1];
                acc += xr[2]*wpt[c*9 + r*3 + 2];
            }
        }
        g_c1[p*BMFW + ((b*MM + m)*FF + f)*WW + w] = acc;
    }
}

// ============================================================
// Kernel 2: batched GEMM over all 3 projections in one launch.
// z in [0,48): p = z/16, n = z%16.
// ============================================================
__global__ __launch_bounds__(256) void gemm_lin_kernel(
    const float* __restrict__ Aq,
    const float* __restrict__ Ak,
    const float* __restrict__ Av)
{
    __shared__ float As[64*17];
    __shared__ float Bs[16*64];
    int z = blockIdx.z;
    int p = z >> 4;
    int n = z & 15;
    int m = n % MM;
    int g0 = blockIdx.y * 64, w0 = blockIdx.x * 64;
    const float* A = (p == 0) ? Aq : (p == 1) ? Ak : Av;
    const float* Ap = A + m*FF*FF;
    const float* Bp = g_c1  + (size_t)p*BMFW + (size_t)n*FF*WW;
    float*       Cp = g_lin + (size_t)p*BMFW + (size_t)n*FF*WW;
    int tx = threadIdx.x, ty = threadIdx.y;
    int tid = ty*16 + tx;

    float acc[4][4] = {};
    for (int f0 = 0; f0 < FF; f0 += 16) {
        {
            int gl = tid / 4;
            int fl = (tid % 4) * 4;
            float4 a4 = *(const float4*)(Ap + (g0+gl)*FF + f0 + fl);
            As[gl*17 + fl+0] = a4.x; As[gl*17 + fl+1] = a4.y;
            As[gl*17 + fl+2] = a4.z; As[gl*17 + fl+3] = a4.w;
        }
        {
            int fl = tid / 16;
            int wl = (tid % 16) * 4;
            *(float4*)(Bs + fl*64 + wl) =
                *(const float4*)(Bp + (f0+fl)*WW + w0 + wl);
        }
        __syncthreads();
        #pragma unroll
        for (int k = 0; k < 16; k++) {
            float a[4];
            #pragma unroll
            for (int i = 0; i < 4; i++) a[i] = As[(ty*4+i)*17 + k];
            float4 b4 = *(const float4*)(Bs + k*64 + tx*4);
            float bf[4] = {b4.x, b4.y, b4.z, b4.w};
            #pragma unroll
            for (int i = 0; i < 4; i++)
                #pragma unroll
                for (int j = 0; j < 4; j++)
                    acc[i][j] += a[i]*bf[j];
        }
        __syncthreads();
    }
    #pragma unroll
    for (int i = 0; i < 4; i++) {
        float4 o4 = make_float4(acc[i][0], acc[i][1], acc[i][2], acc[i][3]);
        *(float4*)(Cp + (g0 + ty*4 + i)*WW + w0 + tx*4) = o4;
    }
}

// ============================================================
// Kernel 3: 1x3 conv across M + rotary, all 3 projections (z).
// ============================================================
__global__ __launch_bounds__(256) void conv2_rot_kernel(
    const float* __restrict__ wq2,
    const float* __restrict__ wk2,
    const float* __restrict__ wv2)
{
    int e = blockIdx.x, b = blockIdx.y, p = blockIdx.z;
    int f0 = 2*e;
    int apply_rot = (p < 2);
    const float* wc2 = (p == 0) ? wq2 : (p == 1) ? wk2 : wv2;
    const float* src = g_lin + (size_t)p*BMFW;
    float*       dst = g_qkv + (size_t)p*BMFW;

    __shared__ float hs[2*MM*(WW+2)];
    __shared__ float wt[MM*MM*3];
    __shared__ float rc[WW], rs[WW];
    int tid = threadIdx.x;

    for (int idx = tid; idx < 2*MM*(WW+2); idx += 256) {
        int rr  = idx / (MM*(WW+2));
        int rem = idx % (MM*(WW+2));
        int mm  = rem / (WW+2);
        int w   = rem % (WW+2) - 1;
        float v = 0.f;
        if (w >= 0 && w < WW)
            v = src[((b*MM + mm)*FF + f0 + rr)*WW + w];
        hs[idx] = v;
    }
    for (int idx = tid; idx < MM*MM*3; idx += 256) wt[idx] = wc2[idx];
    if (apply_rot) {
        int i = e % (HD/2);
        for (int w = tid; w < WW; w += 256) {
            rc[w] = g_rotc[i*WW + w];
            rs[w] = g_rots[i*WW + w];
        }
    }
    __syncthreads();

    for (int o = tid; o < MM*WW; o += 256) {
        int m = o / WW, w = o % WW;
        float c0 = 0.f, c1 = 0.f;
        #pragma unroll
        for (int mm = 0; mm < MM; mm++) {
            float k0 = wt[(m*MM+mm)*3+0];
            float k1 = wt[(m*MM+mm)*3+1];
            float k2 = wt[(m*MM+mm)*3+2];
            const float* h0 = hs + mm*(WW+2) + w;
            const float* h1 = hs + (MM+mm)*(WW+2) + w;
            c0 += h0[0]*k0 + h0[1]*k1 + h0[2]*k2;
            c1 += h1[0]*k0 + h1[1]*k1 + h1[2]*k2;
        }
        float o0 = c0, o1 = c1;
        if (apply_rot) {
            float cs = rc[w], sn = rs[w];
            o0 = c0*cs - c1*sn;
            o1 = c1*cs + c0*sn;
        }
        dst[((b*MM + m)*FF + f0    )*WW + w] = o0;
        dst[((b*MM + m)*FF + f0 + 1)*WW + w] = o1;
    }
}

// ============================================================
// Kernel 4: attention per (b,m,h). 512 threads, 16 warps.
// Per it: each warp does 2 rows. Pq prefetched to regs, Q loads
// software-pipelined over c, PV j-unrolled x4 with float4 p.
// ============================================================
#define KPAD 36

__global__ __launch_bounds__(512, 1) void attn_kernel(
    const float* __restrict__ prev_qk,
    float* __restrict__ qk_out)
{
    int bid = blockIdx.x;
    int h = bid % HH;
    int m = (bid / HH) % MM;
    int b =  bid / (HH*MM);

    extern __shared__ float sm[];
    float* Ks   = sm;                 // [WW][KPAD]
    float* Vs   = Ks + WW*KPAD;       // [WW][32]
    float* ps   = Vs + WW*32;         // [32 rows][WW]
    float* sinv = ps + 32*WW;         // [32]

    int tid  = threadIdx.x;
    int lane = tid & 31, wq = tid >> 5;   // wq in [0,16)

    const float* Qb = g_qkv + 0*BMFW + ((b*MM+m)*FF + h*HD)*WW;
    const float* Kb = g_qkv + 1*BMFW + ((b*MM+m)*FF + h*HD)*WW;
    const float* Vb = g_qkv + 2*BMFW + ((b*MM+m)*FF + h*HD)*WW;
    size_t sbase = (size_t)((b*MM+m)*HH + h) * WW * WW;
    const float* Pq   = prev_qk + sbase;
    float*       Sout = qk_out  + sbase;

    for (int idx = tid; idx < HD*WW; idx += 512) {
        int d = idx >> 9, w = idx & 511;
        Ks[w*KPAD + d] = Kb[d*WW + w];
        Vs[w*32   + d] = Vb[d*WW + w];
    }
    __syncthreads();

    const float scale = 0.0625f;  // 1/sqrt(256)

    for (int it = 0; it < 16; it++) {
        int r0 = it*32 + wq*2;

        // ---- prefetch prev_qk for both rows into regs (hidden by S compute) ----
        float pq[2][16];
        #pragma unroll
        for (int rr = 0; rr < 2; rr++)
            #pragma unroll
            for (int i = 0; i < 16; i++)
                pq[rr][i] = __ldg(Pq + (size_t)(r0+rr)*WW + i*32 + lane);

        // ---- S: 2 rows x 512 cols, Q software-pipelined over c ----
        float sacc[2][16];
        #pragma unroll
        for (int rr = 0; rr < 2; rr++)
            #pragma unroll
            for (int i = 0; i < 16; i++) sacc[rr][i] = 0.f;

        float4 qv[2];
        #pragma unroll
        for (int rr = 0; rr < 2; rr++) {
            int r = r0 + rr;
            qv[rr].x = Qb[0*WW + r]; qv[rr].y = Qb[1*WW + r];
            qv[rr].z = Qb[2*WW + r]; qv[rr].w = Qb[3*WW + r];
        }

        #pragma unroll
        for (int c = 0; c < 8; c++) {
            float4 qn[2];
            if (c < 7) {
                #pragma unroll
                for (int rr = 0; rr < 2; rr++) {
                    int r = r0 + rr;
                    qn[rr].x = Qb[((c+1)*4+0)*WW + r];
                    qn[rr].y = Qb[((c+1)*4+1)*WW + r];
                    qn[rr].z = Qb[((c+1)*4+2)*WW + r];
                    qn[rr].w = Qb[((c+1)*4+3)*WW + r];
                }
            }
            #pragma unroll
            for (int i = 0; i < 16; i++) {
                const float4 k4 = *(const float4*)(Ks + (i*32+lane)*KPAD + c*4);
                #pragma unroll
                for (int rr = 0; rr < 2; rr++) {
                    sacc[rr][i] += qv[rr].x*k4.x + qv[rr].y*k4.y
                                 + qv[rr].z*k4.z + qv[rr].w*k4.w;
                }
            }
            if (c < 7) { qv[0] = qn[0]; qv[1] = qn[1]; }
        }

        // ---- scale + prev (regs), store S, softmax ----
        #pragma unroll
        for (int rr = 0; rr < 2; rr++) {
            int r = r0 + rr;
            float mx = -1e30f;
            #pragma unroll
            for (int i = 0; i < 16; i++) {
                float s = fmaf(sacc[rr][i], scale, pq[rr][i]);
                Sout[(size_t)r*WW + i*32 + lane] = s;
                sacc[rr][i] = s;
                mx = fmaxf(mx, s);
            }
            #pragma unroll
            for (int o = 16; o > 0; o >>= 1)
                mx = fmaxf(mx, __shfl_xor_sync(0xffffffffu, mx, o));

            float sum = 0.f;
            float* pr = ps + (wq*2 + rr)*WW;
            #pragma unroll
            for (int i = 0; i < 16; i++) {
                float ev = __expf(sacc[rr][i] - mx);
                pr[i*32 + lane] = ev;
                sum += ev;
            }
            #pragma unroll
            for (int o = 16; o > 0; o >>= 1)
                sum += __shfl_xor_sync(0xffffffffu, sum, o);
            if (lane == 0) sinv[wq*2 + rr] = 1.0f / sum;
        }
        __syncwarp();

        // ---- PV: lane = (rsub in [0,2), dg in [0,16)), float2 per dg ----
        int dg = lane & 15, rsub = lane >> 4;
        const float* pr = ps + (wq*2 + rsub)*WW;
        float2 acc = make_float2(0.f, 0.f);
        #pragma unroll 2
        for (int j = 0; j < WW; j += 4) {
            float4 p4 = *(const float4*)(pr + j);
            float2 v0 = *(const float2*)(Vs + (j+0)*32 + dg*2);
            float2 v1 = *(const float2*)(Vs + (j+1)*32 + dg*2);
            float2 v2 = *(const float2*)(Vs + (j+2)*32 + dg*2);
            float2 v3 = *(const float2*)(Vs + (j+3)*32 + dg*2);
            acc.x += p4.x*v0.x + p4.y*v1.x + p4.z*v2.x + p4.w*v3.x;
            acc.y += p4.x*v0.y + p4.y*v1.y + p4.z*v2.y + p4.w*v3.y;
        }
        float is = sinv[wq*2 + rsub];
        acc.x *= is; acc.y *= is;
        int r = r0 + rsub;
        *(float2*)(g_at + ((size_t)(b*MM+m)*WW + r)*FF + h*HD + dg*2) = acc;
        __syncwarp();
    }
}

// ============================================================
// Kernel 5: out projection.
// ============================================================
__global__ __launch_bounds__(256) void gemm_out_kernel(
    const float* __restrict__ A,
    const float* __restrict__ Bt,
    float* __restrict__ Cx)
{
    __shared__ float As[64*17];
    __shared__ float Bs[64*17];
    int n = blockIdx.z;
    int m = n % MM;
    int g0 = blockIdx.y * 64, w0 = blockIdx.x * 64;
    const float* Ap = A  + m*FF*FF;
    const float* Bp = Bt + (size_t)n*WW*FF;
    int tx = threadIdx.x, ty = threadIdx.y;
    int tid = ty*16 + tx;

    float acc[4][4] = {};
    for (int f0 = 0; f0 < FF; f0 += 16) {
        int gl = tid / 4;
        int fl = (tid % 4) * 4;
        float4 a4 = *(const float4*)(Ap + (g0+gl)*FF + f0 + fl);
        As[gl*17 + fl+0] = a4.x; As[gl*17 + fl+1] = a4.y;
        As[gl*17 + fl+2] = a4.z; As[gl*17 + fl+3] = a4.w;
        float4 b4 = *(const float4*)(Bp + (size_t)(w0+gl)*FF + f0 + fl);
        Bs[gl*17 + fl+0] = b4.x; Bs[gl*17 + fl+1] = b4.y;
        Bs[gl*17 + fl+2] = b4.z; Bs[gl*17 + fl+3] = b4.w;
        __syncthreads();
        #pragma unroll
        for (int k = 0; k < 16; k++) {
            float a[4], bf[4];
            #pragma unroll
            for (int i = 0; i < 4; i++) a[i]  = As[(ty*4+i)*17 + k];
            #pragma unroll
            for (int j = 0; j < 4; j++) bf[j] = Bs[(tx*4+j)*17 + k];
            #pragma unroll
            for (int i = 0; i < 4; i++)
                #pragma unroll
                for (int j = 0; j < 4; j++)
                    acc[i][j] += a[i]*bf[j];
        }
        __syncthreads();
    }
    #pragma unroll
    for (int i = 0; i < 4; i++) {
        float4 o4 = make_float4(acc[i][0], acc[i][1], acc[i][2], acc[i][3]);
        *(float4*)(Cx + ((size_t)n*FF + g0 + ty*4 + i)*WW + w0 + tx*4) = o4;
    }
}

// ============================================================
extern "C" void kernel_launch(void* const* d_in, const int* in_sizes, int n_in,
                              void* d_out, int out_size)
{
    const float* x       = (const float*)d_in[0];
    const float* prev_qk = (const float*)d_in[1];
    const float* ow      = (const float*)d_in[11];

    float* out_ptr = (float*)d_out;                // (B,M,F,W) first
    float* qk_ptr  = out_ptr + (size_t)BMFW;       // (B,M,H,W,W) second

    float* p_at;
    cudaGetSymbolAddress((void**)&p_at, g_at);

    // rotary table
    rot_table_kernel<<<16, WW>>>();

    // conv1 (all three projections)
    int conv1_smem = (3*CC*(WW+2) + 3*MM*CC*9) * 4;
    cudaFuncSetAttribute(conv1_kernel,
        cudaFuncAttributeMaxDynamicSharedMemorySize, conv1_smem);
    conv1_kernel<<<dim3(FF, BB), 256, conv1_smem>>>(
        x, (const float*)d_in[2], (const float*)d_in[5], (const float*)d_in[8]);

    // all lin GEMMs in one launch
    gemm_lin_kernel<<<dim3(WW/64, FF/64, 3*BB*MM), dim3(16,16)>>>(
        (const float*)d_in[3], (const float*)d_in[6], (const float*)d_in[9]);

    // all conv2(+rotary) in one launch
    conv2_rot_kernel<<<dim3(FF/2, BB, 3), 256>>>(
        (const float*)d_in[4], (const float*)d_in[7], (const float*)d_in[10]);

    // attention
    int attn_smem = (WW*KPAD + WW*32 + 32*WW + 32) * 4;  // ~205 KB
    cudaFuncSetAttribute(attn_kernel,
        cudaFuncAttributeMaxDynamicSharedMemorySize, attn_smem);
    attn_kernel<<<BB*MM*HH, 512, attn_smem>>>(prev_qk, qk_ptr);

    // output projection
    gemm_out_kernel<<<dim3(WW/64, FF/64, BB*MM), dim3(16,16)>>>(ow, p_at, out_ptr);
}

// round 6
// speedup vs baseline: 2.5039x; 1.0350x over previous
#include <cuda_runtime.h>
#include <math.h>

#define BB 2
#define CC 8
#define MM 8
#define HH 8
#define FF 256
#define WW 512
#define HD 32
#define BMFW (BB*MM*FF*WW)   // 2,097,152

// ---- scratch (static device memory; no allocation) ----
__device__ float g_c1[3*BMFW];   // conv1 outputs for q,k,v
__device__ float g_lin[3*BMFW];  // lin outputs q,k,v
__device__ float g_qkv[3*BMFW];  // q,k,v post conv2(+rotary), layout [b][m][f][w]
__device__ float g_at[BMFW];     // attention out, layout [b][m][w][f]
__device__ float g_rotc[16*WW];  // rotary cos table [i][w]
__device__ float g_rots[16*WW];  // rotary sin table [i][w]

// ============================================================
// Kernel 0: rotary table
// ============================================================
__global__ void rot_table_kernel()
{
    int i = blockIdx.x, w = threadIdx.x;
    float invf = expf(-(float)i * (9.210340371976184f / 16.0f));
    float sn, cs;
    sincosf((float)w * invf, &sn, &cs);
    g_rotc[i*WW + w] = cs;
    g_rots[i*WW + w] = sn;
}

// ============================================================
// Kernel 1: 3x3 conv, 8->8 ch, all three projections at once.
// ============================================================
__global__ __launch_bounds__(256) void conv1_kernel(
    const float* __restrict__ x,
    const float* __restrict__ wq,
    const float* __restrict__ wk,
    const float* __restrict__ wv)
{
    int f = blockIdx.x, b = blockIdx.y;
    extern __shared__ float sm[];
    float* xs = sm;                      // [3][CC][WW+2]
    float* wt = sm + 3*CC*(WW+2);        // [3][MM][CC][9]
    int tid = threadIdx.x;

    for (int idx = tid; idx < 3*CC*(WW+2); idx += 256) {
        int r   = idx / (CC*(WW+2));
        int rem = idx % (CC*(WW+2));
        int c   = rem / (WW+2);
        int w   = rem % (WW+2) - 1;
        int fr  = f + r - 1;
        float v = 0.f;
        if (fr >= 0 && fr < FF && w >= 0 && w < WW)
            v = x[((b*CC + c)*FF + fr)*WW + w];
        xs[idx] = v;
    }
    for (int idx = tid; idx < MM*CC*9; idx += 256) {
        wt[idx]              = wq[idx];
        wt[idx +   MM*CC*9]  = wk[idx];
        wt[idx + 2*MM*CC*9]  = wv[idx];
    }
    __syncthreads();

    for (int o = tid; o < 3*MM*WW; o += 256) {
        int p = o / (MM*WW);
        int m = (o / WW) % MM;
        int w = o % WW;
        const float* wpt = wt + (p*MM + m)*CC*9;
        float acc = 0.f;
        #pragma unroll
        for (int c = 0; c < CC; c++) {
            #pragma unroll
            for (int r = 0; r < 3; r++) {
                const float* xr = xs + (r*CC + c)*(WW+2) + w;
                acc += xr[0]*wpt[c*9 + r*3 + 0];
                acc += xr[1]*wpt[c*9 + r*3 + 1];
                acc += xr[2]*wpt[c*9 + r*3 + 2];
            }
        }
        g_c1[p*BMFW + ((b*MM + m)*FF + f)*WW + w] = acc;
    }
}

// ============================================================
// Kernel 2: batched GEMM, 128x64 tiles, 8x4 microtile.
// z in [0,48): p = z/16, n = z%16.
// ============================================================
__global__ __launch_bounds__(256) void gemm_lin_kernel(
    const float* __restrict__ Aq,
    const float* __restrict__ Ak,
    const float* __restrict__ Av)
{
    __shared__ float As[128*17];
    __shared__ float Bs[16*64];
    int z = blockIdx.z;
    int p = z >> 4;
    int n = z & 15;
    int m = n % MM;
    int g0 = blockIdx.y * 128, w0 = blockIdx.x * 64;
    const float* A = (p == 0) ? Aq : (p == 1) ? Ak : Av;
    const float* Ap = A + m*FF*FF;
    const float* Bp = g_c1  + (size_t)p*BMFW + (size_t)n*FF*WW;
    float*       Cp = g_lin + (size_t)p*BMFW + (size_t)n*FF*WW;
    int tx = threadIdx.x, ty = threadIdx.y;
    int tid = ty*16 + tx;

    float acc[8][4] = {};
    for (int f0 = 0; f0 < FF; f0 += 16) {
        #pragma unroll
        for (int u = 0; u < 2; u++) {
            int idx = tid + u*256;
            int r = idx >> 2;
            int c4 = (idx & 3) * 4;
            float4 a4 = *(const float4*)(Ap + (g0+r)*FF + f0 + c4);
            As[r*17 + c4+0] = a4.x; As[r*17 + c4+1] = a4.y;
            As[r*17 + c4+2] = a4.z; As[r*17 + c4+3] = a4.w;
        }
        {
            int fl = tid >> 4;
            int wl = (tid & 15) * 4;
            *(float4*)(Bs + fl*64 + wl) =
                *(const float4*)(Bp + (f0+fl)*WW + w0 + wl);
        }
        __syncthreads();
        #pragma unroll
        for (int k = 0; k < 16; k++) {
            float a[8];
            #pragma unroll
            for (int i = 0; i < 8; i++) a[i] = As[(ty*8+i)*17 + k];
            float4 b4 = *(const float4*)(Bs + k*64 + tx*4);
            float bf[4] = {b4.x, b4.y, b4.z, b4.w};
            #pragma unroll
            for (int i = 0; i < 8; i++)
                #pragma unroll
                for (int j = 0; j < 4; j++)
                    acc[i][j] += a[i]*bf[j];
        }
        __syncthreads();
    }
    #pragma unroll
    for (int i = 0; i < 8; i++) {
        float4 o4 = make_float4(acc[i][0], acc[i][1], acc[i][2], acc[i][3]);
        *(float4*)(Cp + (g0 + ty*8 + i)*WW + w0 + tx*4) = o4;
    }
}

// ============================================================
// Kernel 3: 1x3 conv across M + rotary, all 3 projections (z).
// ============================================================
__global__ __launch_bounds__(256) void conv2_rot_kernel(
    const float* __restrict__ wq2,
    const float* __restrict__ wk2,
    const float* __restrict__ wv2)
{
    int e = blockIdx.x, b = blockIdx.y, p = blockIdx.z;
    int f0 = 2*e;
    int apply_rot = (p < 2);
    const float* wc2 = (p == 0) ? wq2 : (p == 1) ? wk2 : wv2;
    const float* src = g_lin + (size_t)p*BMFW;
    float*       dst = g_qkv + (size_t)p*BMFW;

    __shared__ float hs[2*MM*(WW+2)];
    __shared__ float wt[MM*MM*3];
    __shared__ float rc[WW], rs[WW];
    int tid = threadIdx.x;

    for (int idx = tid; idx < 2*MM*(WW+2); idx += 256) {
        int rr  = idx / (MM*(WW+2));
        int rem = idx % (MM*(WW+2));
        int mm  = rem / (WW+2);
        int w   = rem % (WW+2) - 1;
        float v = 0.f;
        if (w >= 0 && w < WW)
            v = src[((b*MM + mm)*FF + f0 + rr)*WW + w];
        hs[idx] = v;
    }
    for (int idx = tid; idx < MM*MM*3; idx += 256) wt[idx] = wc2[idx];
    if (apply_rot) {
        int i = e % (HD/2);
        for (int w = tid; w < WW; w += 256) {
            rc[w] = g_rotc[i*WW + w];
            rs[w] = g_rots[i*WW + w];
        }
    }
    __syncthreads();

    for (int o = tid; o < MM*WW; o += 256) {
        int m = o / WW, w = o % WW;
        float c0 = 0.f, c1 = 0.f;
        #pragma unroll
        for (int mm = 0; mm < MM; mm++) {
            float k0 = wt[(m*MM+mm)*3+0];
            float k1 = wt[(m*MM+mm)*3+1];
            float k2 = wt[(m*MM+mm)*3+2];
            const float* h0 = hs + mm*(WW+2) + w;
            const float* h1 = hs + (MM+mm)*(WW+2) + w;
            c0 += h0[0]*k0 + h0[1]*k1 + h0[2]*k2;
            c1 += h1[0]*k0 + h1[1]*k1 + h1[2]*k2;
        }
        float o0 = c0, o1 = c1;
        if (apply_rot) {
            float cs = rc[w], sn = rs[w];
            o0 = c0*cs - c1*sn;
            o1 = c1*cs + c0*sn;
        }
        dst[((b*MM + m)*FF + f0    )*WW + w] = o0;
        dst[((b*MM + m)*FF + f0 + 1)*WW + w] = o1;
    }
}

// ============================================================
// Kernel 4: attention per (b,m,h). 512 threads, 16 warps.
// S: 2 rows/warp register-blocked. PV: cross-warp 4 rows/warp
// with j-halved partials + smem pair reduction (all fp32).
// ============================================================
#define KPAD 36

__global__ __launch_bounds__(512, 1) void attn_kernel(
    const float* __restrict__ prev_qk,
    float* __restrict__ qk_out)
{
    int bid = blockIdx.x;
    int h = bid % HH;
    int m = (bid / HH) % MM;
    int b =  bid / (HH*MM);

    extern __shared__ float sm[];
    float* Ks    = sm;                  // [WW][KPAD]    73728 B
    float* Vs    = Ks + WW*KPAD;        // [WW][32]      65536 B
    float* ps    = Vs + WW*32;          // [32][WW]      65536 B
    float* Vpart = ps + 32*WW;          // [2][32][32]    8192 B
    float* sinv  = Vpart + 2*32*32;     // [32]

    int tid  = threadIdx.x;
    int lane = tid & 31, wq = tid >> 5;   // wq in [0,16)

    const float* Qb = g_qkv + 0*BMFW + ((b*MM+m)*FF + h*HD)*WW;
    const float* Kb = g_qkv + 1*BMFW + ((b*MM+m)*FF + h*HD)*WW;
    const float* Vb = g_qkv + 2*BMFW + ((b*MM+m)*FF + h*HD)*WW;
    size_t sbase = (size_t)((b*MM+m)*HH + h) * WW * WW;
    const float* Pq   = prev_qk + sbase;
    float*       Sout = qk_out  + sbase;
    float*       At   = g_at + (size_t)(b*MM+m)*WW*FF + h*HD;

    for (int idx = tid; idx < HD*WW; idx += 512) {
        int d = idx >> 9, w = idx & 511;
        Ks[w*KPAD + d] = Kb[d*WW + w];
        Vs[w*32   + d] = Vb[d*WW + w];
    }
    __syncthreads();

    const float scale = 0.0625f;  // 1/sqrt(256)

    for (int it = 0; it < 16; it++) {
        int r0 = it*32 + wq*2;

        // ---- prefetch prev_qk for both rows into regs ----
        float pq[2][16];
        #pragma unroll
        for (int rr = 0; rr < 2; rr++)
            #pragma unroll
            for (int i = 0; i < 16; i++)
                pq[rr][i] = __ldg(Pq + (size_t)(r0+rr)*WW + i*32 + lane);

        // ---- S: 2 rows x 512 cols, Q software-pipelined over c ----
        float sacc[2][16];
        #pragma unroll
        for (int rr = 0; rr < 2; rr++)
            #pragma unroll
            for (int i = 0; i < 16; i++) sacc[rr][i] = 0.f;

        float4 qv[2];
        #pragma unroll
        for (int rr = 0; rr < 2; rr++) {
            int r = r0 + rr;
            qv[rr].x = Qb[0*WW + r]; qv[rr].y = Qb[1*WW + r];
            qv[rr].z = Qb[2*WW + r]; qv[rr].w = Qb[3*WW + r];
        }

        #pragma unroll
        for (int c = 0; c < 8; c++) {
            float4 qn[2];
            if (c < 7) {
                #pragma unroll
                for (int rr = 0; rr < 2; rr++) {
                    int r = r0 + rr;
                    qn[rr].x = Qb[((c+1)*4+0)*WW + r];
                    qn[rr].y = Qb[((c+1)*4+1)*WW + r];
                    qn[rr].z = Qb[((c+1)*4+2)*WW + r];
                    qn[rr].w = Qb[((c+1)*4+3)*WW + r];
                }
            }
            #pragma unroll
            for (int i = 0; i < 16; i++) {
                const float4 k4 = *(const float4*)(Ks + (i*32+lane)*KPAD + c*4);
                #pragma unroll
                for (int rr = 0; rr < 2; rr++) {
                    sacc[rr][i] += qv[rr].x*k4.x + qv[rr].y*k4.y
                                 + qv[rr].z*k4.z + qv[rr].w*k4.w;
                }
            }
            if (c < 7) { qv[0] = qn[0]; qv[1] = qn[1]; }
        }

        // ---- scale + prev (regs), store S, softmax ----
        #pragma unroll
        for (int rr = 0; rr < 2; rr++) {
            int r = r0 + rr;
            float mx = -1e30f;
            #pragma unroll
            for (int i = 0; i < 16; i++) {
                float s = fmaf(sacc[rr][i], scale, pq[rr][i]);
                Sout[(size_t)r*WW + i*32 + lane] = s;
                sacc[rr][i] = s;
                mx = fmaxf(mx, s);
            }
            #pragma unroll
            for (int o = 16; o > 0; o >>= 1)
                mx = fmaxf(mx, __shfl_xor_sync(0xffffffffu, mx, o));

            float sum = 0.f;
            float* pr = ps + (wq*2 + rr)*WW;
            #pragma unroll
            for (int i = 0; i < 16; i++) {
                float ev = __expf(sacc[rr][i] - mx);
                pr[i*32 + lane] = ev;
                sum += ev;
            }
            #pragma unroll
            for (int o = 16; o > 0; o >>= 1)
                sum += __shfl_xor_sync(0xffffffffu, sum, o);
            if (lane == 0) sinv[wq*2 + rr] = 1.0f / sum;
        }
        __syncthreads();

        // ---- PV: warp = (row-group rg of 4 rows, j-half jh); d = lane ----
        {
            int rg = wq & 7, jh = wq >> 3;
            int jbase = jh * 256;
            const float* p0 = ps + (rg*4+0)*WW + jbase;
            const float* p1 = ps + (rg*4+1)*WW + jbase;
            const float* p2 = ps + (rg*4+2)*WW + jbase;
            const float* p3 = ps + (rg*4+3)*WW + jbase;
            const float* vp = Vs + jbase*32 + lane;
            float a0=0.f, a1=0.f, a2=0.f, a3=0.f;
            #pragma unroll 2
            for (int j = 0; j < 256; j += 4) {
                float4 pa = *(const float4*)(p0 + j);
                float4 pb = *(const float4*)(p1 + j);
                float4 pc = *(const float4*)(p2 + j);
                float4 pd = *(const float4*)(p3 + j);
                float v0 = vp[(j+0)*32];
                float v1 = vp[(j+1)*32];
                float v2 = vp[(j+2)*32];
                float v3 = vp[(j+3)*32];
                a0 += pa.x*v0 + pa.y*v1 + pa.z*v2 + pa.w*v3;
                a1 += pb.x*v0 + pb.y*v1 + pb.z*v2 + pb.w*v3;
                a2 += pc.x*v0 + pc.y*v1 + pc.z*v2 + pc.w*v3;
                a3 += pd.x*v0 + pd.y*v1 + pd.z*v2 + pd.w*v3;
            }
            float* vo = Vpart + (jh*32 + rg*4)*32 + lane;
            vo[0]   = a0;
            vo[32]  = a1;
            vo[64]  = a2;
            vo[96]  = a3;
        }
        __syncthreads();

        // ---- pair-reduce + scale + store (1024 values, 2 per thread) ----
        #pragma unroll
        for (int u = 0; u < 2; u++) {
            int idx = tid + u*512;
            int r = idx >> 5, d = idx & 31;
            float s = (Vpart[r*32 + d] + Vpart[(32+r)*32 + d]) * sinv[r];
            At[(size_t)(it*32 + r)*FF + d] = s;
        }
    }
}

// ============================================================
// Kernel 5: out projection, 128x64 tiles, 8x4 microtile.
// ============================================================
__global__ __launch_bounds__(256) void gemm_out_kernel(
    const float* __restrict__ A,
    const float* __restrict__ Bt,
    float* __restrict__ Cx)
{
    __shared__ float As[128*17];
    __shared__ float Bs[64*17];
    int n = blockIdx.z;
    int m = n % MM;
    int g0 = blockIdx.y * 128, w0 = blockIdx.x * 64;
    const float* Ap = A  + m*FF*FF;
    const float* Bp = Bt + (size_t)n*WW*FF;
    int tx = threadIdx.x, ty = threadIdx.y;
    int tid = ty*16 + tx;

    float acc[8][4] = {};
    for (int f0 = 0; f0 < FF; f0 += 16) {
        #pragma unroll
        for (int u = 0; u < 2; u++) {
            int idx = tid + u*256;
            int r = idx >> 2;
            int c4 = (idx & 3) * 4;
            float4 a4 = *(const float4*)(Ap + (g0+r)*FF + f0 + c4);
            As[r*17 + c4+0] = a4.x; As[r*17 + c4+1] = a4.y;
            As[r*17 + c4+2] = a4.z; As[r*17 + c4+3] = a4.w;
        }
        {
            int wl = tid >> 2;
            int c4 = (tid & 3) * 4;
            float4 b4 = *(const float4*)(Bp + (size_t)(w0+wl)*FF + f0 + c4);
            Bs[wl*17 + c4+0] = b4.x; Bs[wl*17 + c4+1] = b4.y;
            Bs[wl*17 + c4+2] = b4.z; Bs[wl*17 + c4+3] = b4.w;
        }
        __syncthreads();
        #pragma unroll
        for (int k = 0; k < 16; k++) {
            float a[8], bf[4];
            #pragma unroll
            for (int i = 0; i < 8; i++) a[i]  = As[(ty*8+i)*17 + k];
            #pragma unroll
            for (int j = 0; j < 4; j++) bf[j] = Bs[(tx*4+j)*17 + k];
            #pragma unroll
            for (int i = 0; i < 8; i++)
                #pragma unroll
                for (int j = 0; j < 4; j++)
                    acc[i][j] += a[i]*bf[j];
        }
        __syncthreads();
    }
    #pragma unroll
    for (int i = 0; i < 8; i++) {
        float4 o4 = make_float4(acc[i][0], acc[i][1], acc[i][2], acc[i][3]);
        *(float4*)(Cx + ((size_t)n*FF + g0 + ty*8 + i)*WW + w0 + tx*4) = o4;
    }
}

// ============================================================
extern "C" void kernel_launch(void* const* d_in, const int* in_sizes, int n_in,
                              void* d_out, int out_size)
{
    const float* x       = (const float*)d_in[0];
    const float* prev_qk = (const float*)d_in[1];
    const float* ow      = (const float*)d_in[11];

    float* out_ptr = (float*)d_out;                // (B,M,F,W) first
    float* qk_ptr  = out_ptr + (size_t)BMFW;       // (B,M,H,W,W) second

    float* p_at;
    cudaGetSymbolAddress((void**)&p_at, g_at);

    // rotary table
    rot_table_kernel<<<16, WW>>>();

    // conv1 (all three projections)
    int conv1_smem = (3*CC*(WW+2) + 3*MM*CC*9) * 4;
    cudaFuncSetAttribute(conv1_kernel,
        cudaFuncAttributeMaxDynamicSharedMemorySize, conv1_smem);
    conv1_kernel<<<dim3(FF, BB), 256, conv1_smem>>>(
        x, (const float*)d_in[2], (const float*)d_in[5], (const float*)d_in[8]);

    // all lin GEMMs in one launch (128x64 tiles)
    gemm_lin_kernel<<<dim3(WW/64, FF/128, 3*BB*MM), dim3(16,16)>>>(
        (const float*)d_in[3], (const float*)d_in[6], (const float*)d_in[9]);

    // all conv2(+rotary) in one launch
    conv2_rot_kernel<<<dim3(FF/2, BB, 3), 256>>>(
        (const float*)d_in[4], (const float*)d_in[7], (const float*)d_in[10]);

    // attention
    int attn_smem = (WW*KPAD + WW*32 + 32*WW + 2*32*32 + 32) * 4;  // 213248 B
    cudaFuncSetAttribute(attn_kernel,
        cudaFuncAttributeMaxDynamicSharedMemorySize, attn_smem);
    attn_kernel<<<BB*MM*HH, 512, attn_smem>>>(prev_qk, qk_ptr);

    // output projection (128x64 tiles)
    gemm_out_kernel<<<dim3(WW/64, FF/128, BB*MM), dim3(16,16)>>>(ow, p_at, out_ptr);
}